// round 14
// baseline (speedup 1.0000x reference)
#include <cuda_runtime.h>
#include <cstdint>

// Autoregressive RNN, HIDDEN=4096, STEPS=2048.
// 128 persistent CTAs x 1024 threads (occ 50%). Warp (rg,c): 8 rows x 512 cols.
// Weight tiers: cols[0,64) regs, [64,256) smem, [256,512) streamed L2.
// Fused (tag,value) uint2 pairs for h and y-partials (R11, -48%).
// R12: split named barrier — workers bar.arrive and flow into the next step;
// only w0 (finisher) bar.syncs, reduces, tanh, publishes. x gathered by w31
// into smem so w0's serial chain is shorter. No full-CTA convergence per step.

#define HIDDEN 4096
#define STEPS  2048
#define NCTA   128
#define NTH    1024
#define H2     (HIDDEN / 2)
#define NREP   8

__device__ unsigned g_epoch;                  // launches completed (replay-safe)
__device__ uint2 g_hpair[2][NREP][HIDDEN];    // (tag, h-bits) pairs
__device__ uint2 g_ppair[2][NREP][NCTA];      // (tag, y-partial-bits) pairs

__device__ __forceinline__ unsigned ld_vol_u32(const unsigned* p) {
    unsigned v;
    asm volatile("ld.global.cg.b32 %0, [%1];" : "=r"(v) : "l"(p) : "memory");
    return v;
}
__device__ __forceinline__ uint4 ld_vol_v4(const uint4* p) {
    uint4 v;
    asm volatile("ld.global.cg.v4.b32 {%0,%1,%2,%3}, [%4];"
                 : "=r"(v.x), "=r"(v.y), "=r"(v.z), "=r"(v.w)
                 : "l"(p) : "memory");
    return v;
}
__device__ __forceinline__ void st_cg_v2(uint2* p, unsigned a, unsigned b) {
    asm volatile("st.global.cg.v2.u32 [%0], {%1,%2};"
                 :: "l"(p), "r"(a), "r"(b) : "memory");
}

__global__ __launch_bounds__(NTH, 1)
void rnn_kernel(const float* __restrict__ inputs,
                const float* __restrict__ W_ih,
                const float* __restrict__ W_hh,
                const float* __restrict__ b_ih,
                const float* __restrict__ b_hh,
                const float* __restrict__ W_out,
                const float* __restrict__ b_out,
                float* __restrict__ out, int out_size)
{
    extern __shared__ float smem[];
    float2* sw2   = (float2*)smem;                    // [32][3][8][32] float2
    float*  h_sw  = smem + 2 * (32 * 3 * 8 * 32);     // 4096 floats
    float*  s_part = h_sw + HIDDEN;                   // [2][256]
    volatile float* s_x = (volatile float*)(s_part + 512);   // [2]

    const int tid = threadIdx.x;
    const int w   = tid >> 5;
    const int l   = tid & 31;
    const int rg  = w >> 3;        // row group 0..3
    const int c   = w & 7;         // column slice 0..7
    const int cta = blockIdx.x;
    const int RB  = cta * 32 + rg * 8;
    const int c512 = c * 512;
    const int grp = cta >> 4;      // replica group (16 CTAs)

    const unsigned ep   = ld_vol_u32(&g_epoch);
    const unsigned base = ep * (unsigned)STEPS;

    // ---- register tier: cols [c512, c512+64) ----
    float2 wreg[8];
    #pragma unroll
    for (int j = 0; j < 8; j++)
        wreg[j] = *(const float2*)&W_hh[(size_t)(RB + j) * HIDDEN + c512 + 2 * l];

    // ---- shared tier: cols [c512+64, c512+256) ----
    for (int s = 0; s < 3; s++)
        for (int j = 0; j < 8; j++)
            sw2[((w * 3 + s) * 8 + j) * 32 + l] =
                *(const float2*)&W_hh[(size_t)(RB + j) * HIDDEN + c512 + 64 + 64 * s + 2 * l];

    for (int idx = tid; idx < HIDDEN; idx += NTH) h_sw[idx] = 0.f;   // h_{-1}=0

    float f_wih = 0.f, f_b = 0.f, f_wout = 0.f;
    if (w == 0) {
        int R  = cta * 32 + l;
        f_wih  = W_ih[R];
        f_b    = b_ih[R] + b_hh[R];
        f_wout = W_out[R];
    }
    const float bo = b_out[0];
    const float x0 = inputs[0];
    const float2* wg2 = (const float2*)W_hh + (size_t)RB * H2 + (c512 >> 1) + 128 + l;

    __syncthreads();

    #pragma unroll 1
    for (int t = 0; t < STEPS; t++) {
        // prefetch streamed q=0 (h-independent; lands during the wait)
        float2 buf[8];
        #pragma unroll
        for (int j = 0; j < 8; j++) buf[j] = __ldcg(wg2 + (size_t)j * H2);

        if (t > 0) {
            const unsigned tgt = base + (unsigned)t;

            // ---- stage h quarter via fused pairs: poll carries the data ----
            const uint4* hp = (const uint4*)&g_hpair[(t - 1) & 1][grp][c512 + rg * 128];
            uint4 a, b4;
            for (;;) {
                a  = ld_vol_v4(hp + l);        // pairs 2l, 2l+1
                b4 = ld_vol_v4(hp + 32 + l);   // pairs 64+2l, 64+2l+1
                bool ok = (a.x >= tgt) & (a.z >= tgt) & (b4.x >= tgt) & (b4.z >= tgt);
                if (__all_sync(0xffffffffu, ok)) break;
                __nanosleep(40);
            }
            float2* dst = (float2*)(h_sw + c512 + rg * 128);
            dst[l]      = make_float2(__uint_as_float(a.y),  __uint_as_float(a.w));
            dst[32 + l] = make_float2(__uint_as_float(b4.y), __uint_as_float(b4.w));

            // ---- w31 gathers x = y_{t-1} into s_x (off the finisher chain) ----
            if (w == 31) {
                const uint4* pp = (const uint4*)&g_ppair[(t - 1) & 1][grp][0];
                uint4 pa, pb;
                for (;;) {
                    pa = ld_vol_v4(pp + l);
                    pb = ld_vol_v4(pp + 32 + l);
                    bool ok = (pa.x >= tgt) & (pa.z >= tgt) & (pb.x >= tgt) & (pb.z >= tgt);
                    if (__all_sync(0xffffffffu, ok)) break;
                    __nanosleep(40);
                }
                float pv = __uint_as_float(pa.y) + __uint_as_float(pa.w)
                         + __uint_as_float(pb.y) + __uint_as_float(pb.w);
                pv += __shfl_xor_sync(0xffffffffu, pv, 16);
                pv += __shfl_xor_sync(0xffffffffu, pv, 8);
                pv += __shfl_xor_sync(0xffffffffu, pv, 4);
                pv += __shfl_xor_sync(0xffffffffu, pv, 2);
                pv += __shfl_xor_sync(0xffffffffu, pv, 1);
                float xv = bo + pv;
                if (l == 0) {
                    s_x[t & 1] = xv;
                    if (cta == 0) out[t - 1] = xv;        // ys[t-1]
                }
            }
        }
        // slice barrier: 4 warps of slice c share staged h
        asm volatile("bar.sync %0, 128;" :: "r"(1 + c) : "memory");

        // ---- matvec: 8 rows x 512 cols; stream interleaved with smem ----
        float acc[8];
        #pragma unroll
        for (int j = 0; j < 8; j++) acc[j] = 0.f;

        const float2* h2 = (const float2*)(h_sw + c512);

        {   // register tier
            float2 hv = h2[l];
            #pragma unroll
            for (int j = 0; j < 8; j++)
                acc[j] = fmaf(wreg[j].y, hv.y, fmaf(wreg[j].x, hv.x, acc[j]));
        }
        {   // stream q0, load q1
            float2 hv = h2[128 + l];
            #pragma unroll
            for (int j = 0; j < 8; j++)
                acc[j] = fmaf(buf[j].y, hv.y, fmaf(buf[j].x, hv.x, acc[j]));
            #pragma unroll
            for (int j = 0; j < 8; j++) buf[j] = __ldcg(wg2 + 32 + (size_t)j * H2);
        }
        {   // smem s0
            float2 hv = h2[32 + l];
            const float2* wp = sw2 + ((w * 3 + 0) * 8) * 32 + l;
            #pragma unroll
            for (int j = 0; j < 8; j++) {
                float2 wv = wp[j * 32];
                acc[j] = fmaf(wv.y, hv.y, fmaf(wv.x, hv.x, acc[j]));
            }
        }
        {   // stream q1, load q2
            float2 hv = h2[160 + l];
            #pragma unroll
            for (int j = 0; j < 8; j++)
                acc[j] = fmaf(buf[j].y, hv.y, fmaf(buf[j].x, hv.x, acc[j]));
            #pragma unroll
            for (int j = 0; j < 8; j++) buf[j] = __ldcg(wg2 + 64 + (size_t)j * H2);
        }
        {   // smem s1
            float2 hv = h2[64 + l];
            const float2* wp = sw2 + ((w * 3 + 1) * 8) * 32 + l;
            #pragma unroll
            for (int j = 0; j < 8; j++) {
                float2 wv = wp[j * 32];
                acc[j] = fmaf(wv.y, hv.y, fmaf(wv.x, hv.x, acc[j]));
            }
        }
        {   // stream q2, load q3
            float2 hv = h2[192 + l];
            #pragma unroll
            for (int j = 0; j < 8; j++)
                acc[j] = fmaf(buf[j].y, hv.y, fmaf(buf[j].x, hv.x, acc[j]));
            #pragma unroll
            for (int j = 0; j < 8; j++) buf[j] = __ldcg(wg2 + 96 + (size_t)j * H2);
        }
        {   // smem s2
            float2 hv = h2[96 + l];
            const float2* wp = sw2 + ((w * 3 + 2) * 8) * 32 + l;
            #pragma unroll
            for (int j = 0; j < 8; j++) {
                float2 wv = wp[j * 32];
                acc[j] = fmaf(wv.y, hv.y, fmaf(wv.x, hv.x, acc[j]));
            }
        }
        {   // stream q3
            float2 hv = h2[224 + l];
            #pragma unroll
            for (int j = 0; j < 8; j++)
                acc[j] = fmaf(buf[j].y, hv.y, fmaf(buf[j].x, hv.x, acc[j]));
        }

        // warp reduce 8 row partials -> s_part[t&1]
        float* spb = s_part + (t & 1) * 256;
        #pragma unroll
        for (int j = 0; j < 8; j++) {
            float v = acc[j];
            v += __shfl_xor_sync(0xffffffffu, v, 16);
            v += __shfl_xor_sync(0xffffffffu, v, 8);
            v += __shfl_xor_sync(0xffffffffu, v, 4);
            v += __shfl_xor_sync(0xffffffffu, v, 2);
            v += __shfl_xor_sync(0xffffffffu, v, 1);
            if (l == 0) spb[(rg * 8 + j) * 8 + c] = v;
        }

        // ---- split barrier: workers arrive and move on; w0 waits+finishes --
        if (w != 0) {
            asm volatile("bar.arrive 15, %0;" :: "r"(NTH) : "memory");
        } else {
            asm volatile("bar.sync 15, %0;" :: "r"(NTH) : "memory");

            const float4* sp4 = (const float4*)(s_part + (t & 1) * 256 + l * 8);
            float4 a = sp4[0], b4 = sp4[1];
            float dot = ((a.x + a.y) + (a.z + a.w)) + ((b4.x + b4.y) + (b4.z + b4.w));
            float x = (t == 0) ? x0 : s_x[t & 1];
            float pre  = fmaf(x, f_wih, f_b + dot);
            float hnew = tanhf(pre);

            const unsigned ntag = base + (unsigned)t + 1u;
            const unsigned hbits = __float_as_uint(hnew);
            #pragma unroll
            for (int rep = 0; rep < NREP; rep++)
                st_cg_v2(&g_hpair[t & 1][rep][cta * 32 + l], ntag, hbits);

            float pv = hnew * f_wout;
            pv += __shfl_xor_sync(0xffffffffu, pv, 16);
            pv += __shfl_xor_sync(0xffffffffu, pv, 8);
            pv += __shfl_xor_sync(0xffffffffu, pv, 4);
            pv += __shfl_xor_sync(0xffffffffu, pv, 2);
            pv += __shfl_xor_sync(0xffffffffu, pv, 1);
            if (l < NREP)
                st_cg_v2(&g_ppair[t & 1][l][cta], ntag, __float_as_uint(pv));

            if (t == STEPS - 1 && out_size >= STEPS + HIDDEN)
                out[STEPS + cta * 32 + l] = hnew;
        }
    }

    // final readout ys[STEPS-1]; then CTA0 bumps the epoch
    if (cta == 0 && w == 0) {
        const unsigned tgt = base + (unsigned)STEPS;
        const uint4* pp = (const uint4*)&g_ppair[(STEPS - 1) & 1][0][0];
        uint4 pa, pb;
        for (;;) {
            pa = ld_vol_v4(pp + l);
            pb = ld_vol_v4(pp + 32 + l);
            bool ok = (pa.x >= tgt) & (pa.z >= tgt) & (pb.x >= tgt) & (pb.z >= tgt);
            if (__all_sync(0xffffffffu, ok)) break;
            __nanosleep(40);
        }
        float pv = __uint_as_float(pa.y) + __uint_as_float(pa.w)
                 + __uint_as_float(pb.y) + __uint_as_float(pb.w);
        pv += __shfl_xor_sync(0xffffffffu, pv, 16);
        pv += __shfl_xor_sync(0xffffffffu, pv, 8);
        pv += __shfl_xor_sync(0xffffffffu, pv, 4);
        pv += __shfl_xor_sync(0xffffffffu, pv, 2);
        pv += __shfl_xor_sync(0xffffffffu, pv, 1);
        if (l == 0) {
            out[STEPS - 1] = bo + pv;
            asm volatile("st.global.cg.b32 [%0], %1;"
                         :: "l"(&g_epoch), "r"(ep + 1u) : "memory");
        }
    }
}

extern "C" void kernel_launch(void* const* d_in, const int* in_sizes, int n_in,
                              void* d_out, int out_size)
{
    const float* inputs = (const float*)d_in[0];
    const float* W_ih   = (const float*)d_in[1];
    const float* W_hh   = (const float*)d_in[2];
    const float* b_ih   = (const float*)d_in[3];
    const float* b_hh   = (const float*)d_in[4];
    const float* W_out  = (const float*)d_in[5];
    const float* b_out  = (const float*)d_in[6];
    float* out = (float*)d_out;

    const int smem_bytes = (2 * 32 * 3 * 8 * 32 + HIDDEN + 512 + 8)
                           * (int)sizeof(float);
    cudaFuncSetAttribute(rnn_kernel,
                         cudaFuncAttributeMaxDynamicSharedMemorySize, smem_bytes);

    rnn_kernel<<<NCTA, NTH, smem_bytes>>>(
        inputs, W_ih, W_hh, b_ih, b_hh, W_out, b_out, out, out_size);
}